// round 2
// baseline (speedup 1.0000x reference)
#include <cuda_runtime.h>
#include <math.h>

#define N      8192
#define D      128
#define NCLS   128
#define NCHUNK 32            // N/256
#define INV_T  5.0f          // 1/T, T=0.2

// ---------------- scratch (device globals; no allocations) ----------------
__device__ float g_invn[N];                 // 1/norm per row
__device__ float g_rowPart[2 * N];          // column-split partial row sums of e
__device__ int   g_ofs[NCLS + 1];           // class offsets
__device__ int   g_chunkBase[NCHUNK][NCLS]; // write base for (chunk, class)
__device__ int   g_order[N];                // row indices grouped by class (stable)
__device__ float g_classLoss[NCLS];
__device__ float g_classN[NCLS];

// ---------------- 1) row norms -> inverse norms ----------------
__global__ void norms_kernel(const float* __restrict__ x) {
    int row  = blockIdx.x * 8 + (threadIdx.x >> 5);
    int lane = threadIdx.x & 31;
    float4 v = *(const float4*)(x + row * D + lane * 4);
    float s = v.x * v.x + v.y * v.y + v.z * v.z + v.w * v.w;
    #pragma unroll
    for (int o = 16; o > 0; o >>= 1) s += __shfl_xor_sync(0xffffffffu, s, o);
    if (lane == 0) g_invn[row] = 1.0f / fmaxf(sqrtf(s), 1e-6f);
}

// ---------------- 2) per-chunk class histogram -> offsets (deterministic) ----------------
__global__ void build_ofs_kernel(const int* __restrict__ label) {
    __shared__ int cnt[NCHUNK][NCLS];   // 16 KB
    __shared__ int tot[NCLS];
    __shared__ int ofs[NCLS];
    int t = threadIdx.x;                // 256 threads
    for (int i = t; i < NCHUNK * NCLS; i += 256) (&cnt[0][0])[i] = 0;
    __syncthreads();
    for (int i = t; i < N; i += 256) atomicAdd(&cnt[i >> 8][label[i]], 1);  // int atomics: deterministic result
    __syncthreads();
    if (t < NCLS) {                     // per-class exclusive scan over chunks
        int run = 0;
        #pragma unroll
        for (int k = 0; k < NCHUNK; k++) { int v = cnt[k][t]; cnt[k][t] = run; run += v; }
        tot[t] = run;
    }
    __syncthreads();
    if (t == 0) {                       // exclusive scan over classes
        int run = 0;
        for (int c = 0; c < NCLS; c++) { ofs[c] = run; g_ofs[c] = run; run += tot[c]; }
        g_ofs[NCLS] = run;
    }
    __syncthreads();
    if (t < NCLS)
        #pragma unroll
        for (int k = 0; k < NCHUNK; k++) g_chunkBase[k][t] = ofs[t] + cnt[k][t];
}

// ---------------- 3) stable scatter within 256-row chunks ----------------
__global__ void scatter_kernel(const int* __restrict__ label) {
    __shared__ unsigned char lab[256];
    int t = threadIdx.x;
    int gi = blockIdx.x * 256 + t;
    int c = label[gi];
    lab[t] = (unsigned char)c;
    __syncthreads();
    int rank = 0;
    for (int j = 0; j < t; j++) rank += (lab[j] == (unsigned char)c);
    g_order[g_chunkBase[blockIdx.x][c] + rank] = gi;
}

// ---------------- 4) fused Gram + exp + row-sum (the heavy kernel) ----------------
// Tile 64 rows x 64 cols, 256 threads (16x16), 4x4 microtile.
// A tile (64 rows, full D) staged transposed in SMEM once per block.
// B staged in 8KB K-chunks of 32. Column range split in 2 halves -> grid 256.
__global__ void gram_kernel(const float* __restrict__ x) {
    __shared__ float As[D][64];   // 32 KB, [d][row]
    __shared__ float Bs[32][64];  // 8 KB,  [d][col]
    const int tid = threadIdx.x;
    const int tx = tid & 15, ty = tid >> 4;
    const int rowTile = blockIdx.x >> 1;
    const int half    = blockIdx.x & 1;
    const int rowBase = rowTile * 64;

    // stage A transposed (64 rows x 128 d) — coalesced float4 reads
    for (int t = tid; t < 64 * 32; t += 256) {
        int r = t >> 5, d4 = t & 31;
        float4 v = *(const float4*)(x + (rowBase + r) * D + d4 * 4);
        As[d4 * 4 + 0][r] = v.x; As[d4 * 4 + 1][r] = v.y;
        As[d4 * 4 + 2][r] = v.z; As[d4 * 4 + 3][r] = v.w;
    }

    float inr[4], rs[4];
    #pragma unroll
    for (int i = 0; i < 4; i++) {
        inr[i] = g_invn[rowBase + ty * 4 + i] * INV_T;  // fold 1/T into row invnorm
        rs[i] = 0.f;
    }

    const int ctBeg = half * 64, ctEnd = ctBeg + 64;
    for (int ct = ctBeg; ct < ctEnd; ct++) {
        const int colBase = ct * 64;
        float acc[4][4] = {};
        for (int kc = 0; kc < 4; kc++) {
            __syncthreads();
            // stage B chunk: 64 cols x 32 d
            for (int t = tid; t < 64 * 8; t += 256) {
                int c = t >> 3, d4 = t & 7;
                float4 v = *(const float4*)(x + (colBase + c) * D + kc * 32 + d4 * 4);
                Bs[d4 * 4 + 0][c] = v.x; Bs[d4 * 4 + 1][c] = v.y;
                Bs[d4 * 4 + 2][c] = v.z; Bs[d4 * 4 + 3][c] = v.w;
            }
            __syncthreads();
            #pragma unroll
            for (int k = 0; k < 32; k++) {
                float4 a = *(const float4*)&As[kc * 32 + k][ty * 4];
                float4 b = *(const float4*)&Bs[k][tx * 4];
                acc[0][0] = fmaf(a.x, b.x, acc[0][0]); acc[0][1] = fmaf(a.x, b.y, acc[0][1]);
                acc[0][2] = fmaf(a.x, b.z, acc[0][2]); acc[0][3] = fmaf(a.x, b.w, acc[0][3]);
                acc[1][0] = fmaf(a.y, b.x, acc[1][0]); acc[1][1] = fmaf(a.y, b.y, acc[1][1]);
                acc[1][2] = fmaf(a.y, b.z, acc[1][2]); acc[1][3] = fmaf(a.y, b.w, acc[1][3]);
                acc[2][0] = fmaf(a.z, b.x, acc[2][0]); acc[2][1] = fmaf(a.z, b.y, acc[2][1]);
                acc[2][2] = fmaf(a.z, b.z, acc[2][2]); acc[2][3] = fmaf(a.z, b.w, acc[2][3]);
                acc[3][0] = fmaf(a.w, b.x, acc[3][0]); acc[3][1] = fmaf(a.w, b.y, acc[3][1]);
                acc[3][2] = fmaf(a.w, b.z, acc[3][2]); acc[3][3] = fmaf(a.w, b.w, acc[3][3]);
            }
        }
        // epilogue: e = exp(sim/T), diag zeroed, accumulate row sums
        const int c0 = colBase + tx * 4;
        float ic0 = g_invn[c0 + 0], ic1 = g_invn[c0 + 1];
        float ic2 = g_invn[c0 + 2], ic3 = g_invn[c0 + 3];
        #pragma unroll
        for (int i = 0; i < 4; i++) {
            int r = rowBase + ty * 4 + i;
            float e0 = (r == c0 + 0) ? 0.f : __expf(acc[i][0] * inr[i] * ic0);
            float e1 = (r == c0 + 1) ? 0.f : __expf(acc[i][1] * inr[i] * ic1);
            float e2 = (r == c0 + 2) ? 0.f : __expf(acc[i][2] * inr[i] * ic2);
            float e3 = (r == c0 + 3) ? 0.f : __expf(acc[i][3] * inr[i] * ic3);
            rs[i] += (e0 + e1) + (e2 + e3);
        }
    }

    // reduce 16 tx-partials per row (deterministic order), write partial totals
    __syncthreads();
    float* red = &Bs[0][0];   // reuse: 64 rows x 16 floats = 4KB
    #pragma unroll
    for (int i = 0; i < 4; i++) red[(ty * 4 + i) * 16 + tx] = rs[i];
    __syncthreads();
    if (tid < 64) {
        float s = 0.f;
        #pragma unroll
        for (int t = 0; t < 16; t++) s += red[tid * 16 + t];
        g_rowPart[half * N + rowBase + tid] = s;
    }
}

// ---------------- 5) per-class positive terms ----------------
// One block per class, 8 warps; warp w handles class members w, w+8, ...
__global__ void class_loss_kernel(const float* __restrict__ x) {
    const int c = blockIdx.x;
    const int base = g_ofs[c];
    const int n = g_ofs[c + 1] - base;
    const int warp = threadIdx.x >> 5, lane = threadIdx.x & 31;

    float lossAcc = 0.f;
    for (int il = warp; il < n; il += 8) {
        const int i = g_order[base + il];
        const float4 xi = *(const float4*)(x + i * D + lane * 4);
        const float invi = g_invn[i] * INV_T;

        float possum = 0.f;
        for (int jl = 0; jl < n; jl++) {
            if (jl == il) continue;
            const int j = g_order[base + jl];
            float4 xj = *(const float4*)(x + j * D + lane * 4);
            float p = xi.x * xj.x + xi.y * xj.y + xi.z * xj.z + xi.w * xj.w;
            #pragma unroll
            for (int o = 16; o > 0; o >>= 1) p += __shfl_xor_sync(0xffffffffu, p, o);
            possum += __expf(p * invi * g_invn[j]);
        }
        const float unsim = (g_rowPart[i] + g_rowPart[N + i]) - possum;

        for (int jl = 0; jl < n; jl++) {
            if (jl == il) continue;
            const int j = g_order[base + jl];
            float4 xj = *(const float4*)(x + j * D + lane * 4);
            float p = xi.x * xj.x + xi.y * xj.y + xi.z * xj.z + xi.w * xj.w;
            #pragma unroll
            for (int o = 16; o > 0; o >>= 1) p += __shfl_xor_sync(0xffffffffu, p, o);
            float s = p * invi * g_invn[j];
            lossAcc += logf(__expf(s) + unsim) - s;
        }
    }

    __shared__ float wsum[8];
    if (lane == 0) wsum[warp] = lossAcc;   // all lanes hold identical value
    __syncthreads();
    if (threadIdx.x == 0) {
        float s = 0.f;
        #pragma unroll
        for (int w = 0; w < 8; w++) s += wsum[w];
        g_classLoss[c] = s;
        g_classN[c] = (float)n * (float)(n - 1);
    }
}

// ---------------- 6) finalize ----------------
__global__ void finalize_kernel(float* __restrict__ out) {
    __shared__ float sl[NCLS], sn[NCLS];
    int t = threadIdx.x;
    sl[t] = g_classLoss[t];
    sn[t] = g_classN[t];
    __syncthreads();
    if (t == 0) {
        float L = 0.f, P = 0.f;
        for (int k = 0; k < NCLS; k++) { L += sl[k]; P += sn[k]; }
        out[0] = L / P;
    }
}

// ---------------- launch ----------------
extern "C" void kernel_launch(void* const* d_in, const int* in_sizes, int n_in,
                              void* d_out, int out_size) {
    const float* x     = (const float*)d_in[0];
    const int*   label = (const int*)d_in[1];   // jax int64 request -> int32 on device (x64 disabled)
    float*       out   = (float*)d_out;

    norms_kernel<<<N / 8, 256>>>(x);
    build_ofs_kernel<<<1, 256>>>(label);
    scatter_kernel<<<NCHUNK, 256>>>(label);
    gram_kernel<<<256, 256>>>(x);
    class_loss_kernel<<<NCLS, 256>>>(x);
    finalize_kernel<<<1, NCLS>>>(out);
}

// round 4
// speedup vs baseline: 4.6172x; 4.6172x over previous
#include <cuda_runtime.h>
#include <cuda_bf16.h>
#include <math.h>
#include <stdint.h>

#define N      8192
#define D      128
#define NCLS   128
#define NCHUNK 32            // N/256
#define TT     128           // gram tile (rows == cols)
#define NT     (N / TT)      // 64 tiles per dim
#define CAP    128           // max class size supported
#define YSTR   132           // padded row stride (floats) for class smem
#define LDAB   272           // bytes per smem tile row: 128 bf16 + 8 pad = 136*2

// ---------------- scratch (device globals; no allocations) ----------------
__device__ float          g_invn[N];
__device__ float          g_y[N * D];          // prescaled: y = x * invn * sqrt(1/T)
__device__ __nv_bfloat16  g_yhi[N * D];
__device__ __nv_bfloat16  g_ylo[N * D];
__device__ float          g_rowPart[NT * N];   // per-coltile partial row sums of e
__device__ float          g_rowTot[N];
__device__ int            g_ofs[NCLS + 1];
__device__ int            g_chunkBase[NCHUNK][NCLS];
__device__ int            g_order[N];
__device__ float          g_classLoss[NCLS];
__device__ float          g_classN[NCLS];

// ---------------- helpers ----------------
__device__ __forceinline__ uint32_t smem_u32(const void* p) {
    uint32_t a;
    asm("{ .reg .u64 t; cvta.to.shared.u64 t, %1; cvt.u32.u64 %0, t; }" : "=r"(a) : "l"(p));
    return a;
}

#define LDSM4(r, addr)                                                           \
    asm volatile("ldmatrix.sync.aligned.m8n8.x4.shared.b16 {%0,%1,%2,%3}, [%4];" \
        : "=r"((r)[0]), "=r"((r)[1]), "=r"((r)[2]), "=r"((r)[3]) : "r"(addr))

#define MMA16816(d, a, b0r, b1r)                                                 \
    asm volatile("mma.sync.aligned.m16n8k16.row.col.f32.bf16.bf16.f32 "          \
        "{%0,%1,%2,%3}, {%4,%5,%6,%7}, {%8,%9}, {%0,%1,%2,%3};"                  \
        : "+f"((d)[0]), "+f"((d)[1]), "+f"((d)[2]), "+f"((d)[3])                 \
        : "r"((a)[0]), "r"((a)[1]), "r"((a)[2]), "r"((a)[3]), "r"(b0r), "r"(b1r))

// ---------------- 1) row norms ----------------
__global__ void norms_kernel(const float* __restrict__ x) {
    int row  = blockIdx.x * 8 + (threadIdx.x >> 5);
    int lane = threadIdx.x & 31;
    float4 v = *(const float4*)(x + row * D + lane * 4);
    float s = v.x * v.x + v.y * v.y + v.z * v.z + v.w * v.w;
    #pragma unroll
    for (int o = 16; o > 0; o >>= 1) s += __shfl_xor_sync(0xffffffffu, s, o);
    if (lane == 0) g_invn[row] = 1.0f / fmaxf(sqrtf(s), 1e-6f);
}

// ---------------- 2) prescale + bf16 hi/lo split ----------------
__global__ void prep_kernel(const float* __restrict__ x) {
    int i = blockIdx.x * 256 + threadIdx.x;   // float4 index
    int row = i >> 5;
    float s = g_invn[row] * 2.2360679774997896f;   // sqrt(1/T)
    float4 v = ((const float4*)x)[i];
    v.x *= s; v.y *= s; v.z *= s; v.w *= s;
    ((float4*)g_y)[i] = v;
    __nv_bfloat16 h0 = __float2bfloat16(v.x), h1 = __float2bfloat16(v.y);
    __nv_bfloat16 h2 = __float2bfloat16(v.z), h3 = __float2bfloat16(v.w);
    __nv_bfloat162* ph = (__nv_bfloat162*)g_yhi;
    __nv_bfloat162* pl = (__nv_bfloat162*)g_ylo;
    ph[i * 2 + 0] = __nv_bfloat162(h0, h1);
    ph[i * 2 + 1] = __nv_bfloat162(h2, h3);
    pl[i * 2 + 0] = __nv_bfloat162(__float2bfloat16(v.x - __bfloat162float(h0)),
                                   __float2bfloat16(v.y - __bfloat162float(h1)));
    pl[i * 2 + 1] = __nv_bfloat162(__float2bfloat16(v.z - __bfloat162float(h2)),
                                   __float2bfloat16(v.w - __bfloat162float(h3)));
}

// ---------------- 3) class offsets (deterministic) ----------------
__global__ void build_ofs_kernel(const int* __restrict__ label) {
    __shared__ int cnt[NCHUNK][NCLS];
    __shared__ int tot[NCLS];
    __shared__ int ofs[NCLS];
    int t = threadIdx.x;
    for (int i = t; i < NCHUNK * NCLS; i += 256) (&cnt[0][0])[i] = 0;
    __syncthreads();
    for (int i = t; i < N; i += 256) atomicAdd(&cnt[i >> 8][label[i]], 1);
    __syncthreads();
    if (t < NCLS) {
        int run = 0;
        #pragma unroll
        for (int k = 0; k < NCHUNK; k++) { int v = cnt[k][t]; cnt[k][t] = run; run += v; }
        tot[t] = run;
    }
    __syncthreads();
    if (t == 0) {
        int run = 0;
        for (int c = 0; c < NCLS; c++) { ofs[c] = run; g_ofs[c] = run; run += tot[c]; }
        g_ofs[NCLS] = run;
    }
    __syncthreads();
    if (t < NCLS)
        #pragma unroll
        for (int k = 0; k < NCHUNK; k++) g_chunkBase[k][t] = ofs[t] + cnt[k][t];
}

// ---------------- 4) stable scatter ----------------
__global__ void scatter_kernel(const int* __restrict__ label) {
    __shared__ unsigned char lab[256];
    int t = threadIdx.x;
    int gi = blockIdx.x * 256 + t;
    int c = label[gi];
    lab[t] = (unsigned char)c;
    __syncthreads();
    int rank = 0;
    for (int j = 0; j < t; j++) rank += (lab[j] == (unsigned char)c);
    g_order[g_chunkBase[blockIdx.x][c] + rank] = gi;
}

// ---------------- 5) HMMA Gram + exp + row-sum ----------------
// 128x128 tile, 8 warps (4M x 2N), warp tile 32x64, m16n8k16 bf16 split (3 products).
#define SM_AHI   0
#define SM_ALO   (128 * LDAB)
#define SM_BHI   (2 * 128 * LDAB)
#define SM_BLO   (3 * 128 * LDAB)
#define SM_TOTAL (4 * 128 * LDAB)     // 139264 B

__global__ void __launch_bounds__(256, 1) gram_hmma() {
    extern __shared__ char smem[];
    const uint32_t sb = smem_u32(smem);
    const int tid = threadIdx.x, wid = tid >> 5, lane = tid & 31;
    const int rt = blockIdx.x >> 6, ct = blockIdx.x & 63;
    const int rowBase = rt * TT, colBase = ct * TT;

    // stage tiles: 128 rows x 16 chunks of 16B per array
    for (int i = tid; i < 128 * 16; i += 256) {
        int r = i >> 4, c8 = i & 15;
        uint32_t off = (uint32_t)r * LDAB + (uint32_t)c8 * 16;
        *(uint4*)(smem + SM_AHI + off) = ((const uint4*)(g_yhi + (size_t)(rowBase + r) * D))[c8];
        *(uint4*)(smem + SM_ALO + off) = ((const uint4*)(g_ylo + (size_t)(rowBase + r) * D))[c8];
        *(uint4*)(smem + SM_BHI + off) = ((const uint4*)(g_yhi + (size_t)(colBase + r) * D))[c8];
        *(uint4*)(smem + SM_BLO + off) = ((const uint4*)(g_ylo + (size_t)(colBase + r) * D))[c8];
    }
    __syncthreads();

    const int wy = wid & 3, wx = wid >> 2;      // warp grid 4(M) x 2(N)
    const int aRow = wy * 32, bRow = wx * 64;

    // ldmatrix lane addressing
    const int aR  = aRow + (lane & 15);
    const int aC  = (lane >> 4) * 16;                       // bytes: *8 elems *2
    const int bR  = bRow + (lane & 7) + ((lane >> 4) << 3);
    const int bC  = ((lane >> 3) & 1) * 16;

    float acc[2][8][4];
    #pragma unroll
    for (int mi = 0; mi < 2; mi++)
        #pragma unroll
        for (int nt = 0; nt < 8; nt++)
            #pragma unroll
            for (int q = 0; q < 4; q++) acc[mi][nt][q] = 0.f;

    #pragma unroll
    for (int kk = 0; kk < 8; kk++) {
        const uint32_t kOff = (uint32_t)kk * 32;            // 16 bf16 = 32 B
        uint32_t ah[2][4], al[2][4], bh[4][4], bl[4][4];
        #pragma unroll
        for (int mi = 0; mi < 2; mi++) {
            uint32_t ad = sb + (uint32_t)(aR + mi * 16) * LDAB + kOff + aC;
            LDSM4(ah[mi], ad + SM_AHI);
            LDSM4(al[mi], ad + SM_ALO);
        }
        #pragma unroll
        for (int ni = 0; ni < 4; ni++) {
            uint32_t bd = sb + (uint32_t)(bR + ni * 16) * LDAB + kOff + bC;
            LDSM4(bh[ni], bd + SM_BHI);
            LDSM4(bl[ni], bd + SM_BLO);
        }
        #pragma unroll
        for (int mi = 0; mi < 2; mi++)
            #pragma unroll
            for (int ni = 0; ni < 4; ni++)
                #pragma unroll
                for (int h = 0; h < 2; h++) {
                    const int nt = ni * 2 + h;
                    MMA16816(acc[mi][nt], ah[mi], bh[ni][h * 2], bh[ni][h * 2 + 1]); // hi*hi
                    MMA16816(acc[mi][nt], ah[mi], bl[ni][h * 2], bl[ni][h * 2 + 1]); // hi*lo
                    MMA16816(acc[mi][nt], al[mi], bh[ni][h * 2], bh[ni][h * 2 + 1]); // lo*hi
                }
    }

    // epilogue: exp + row sums (diag zeroed), deterministic reduction
    const int g = lane >> 2, t4 = lane & 3;
    float rsum[2][2] = {{0.f, 0.f}, {0.f, 0.f}};   // [mi][0: row g, 1: row g+8]
    #pragma unroll
    for (int mi = 0; mi < 2; mi++) {
        const int row0 = rowBase + aRow + mi * 16 + g;
        const int row1 = row0 + 8;
        #pragma unroll
        for (int nt = 0; nt < 8; nt++) {
            const int gc = colBase + bRow + nt * 8 + t4 * 2;
            float e0 = (row0 == gc    ) ? 0.f : __expf(acc[mi][nt][0]);
            float e1 = (row0 == gc + 1) ? 0.f : __expf(acc[mi][nt][1]);
            float e2 = (row1 == gc    ) ? 0.f : __expf(acc[mi][nt][2]);
            float e3 = (row1 == gc + 1) ? 0.f : __expf(acc[mi][nt][3]);
            rsum[mi][0] += e0 + e1;
            rsum[mi][1] += e2 + e3;
        }
    }
    __syncthreads();                               // done reading tiles; reuse smem
    float* red = (float*)smem;                     // [128 rows][2 wx]
    #pragma unroll
    for (int mi = 0; mi < 2; mi++)
        #pragma unroll
        for (int hrow = 0; hrow < 2; hrow++) {
            float s = rsum[mi][hrow];
            s += __shfl_xor_sync(0xffffffffu, s, 1);
            s += __shfl_xor_sync(0xffffffffu, s, 2);
            if (t4 == 0) red[(aRow + mi * 16 + hrow * 8 + g) * 2 + wx] = s;
        }
    __syncthreads();
    if (tid < 128)
        g_rowPart[(size_t)ct * N + rowBase + tid] = red[tid * 2] + red[tid * 2 + 1];
}

// ---------------- 6) row totals (fixed order, deterministic) ----------------
__global__ void rowtot_kernel() {
    int r = blockIdx.x * 256 + threadIdx.x;
    float s = 0.f;
    #pragma unroll
    for (int c = 0; c < NT; c++) s += g_rowPart[(size_t)c * N + r];
    g_rowTot[r] = s;
}

// ---------------- 7) per-class loss ----------------
#define CLS_SMEM (CAP * YSTR * 4 + CAP * CAP * 4)
__global__ void __launch_bounds__(256, 1) class_loss_kernel() {
    extern __shared__ char cs[];
    float* ys = (float*)cs;
    float* S  = (float*)(cs + CAP * YSTR * 4);
    __shared__ int   gidx[CAP];
    __shared__ float unsimS[CAP];
    __shared__ float tr[256];
    const int c = blockIdx.x, tid = threadIdx.x;
    const int base = g_ofs[c];
    int n = g_ofs[c + 1] - base;
    if (n > CAP) n = CAP;

    for (int i = tid; i < n; i += 256) gidx[i] = g_order[base + i];
    __syncthreads();
    for (int i = tid; i < n * 32; i += 256) {
        int m = i >> 5, q = i & 31;
        *(float4*)(ys + m * YSTR + q * 4) = ((const float4*)(g_y + (size_t)gidx[m] * D))[q];
    }
    __syncthreads();

    const int nn = n * n;
    // phase A: pair dots -> S (dot = sim/T, y prescaled)
    for (int p = tid; p < nn; p += 256) {
        int i = p / n, j = p - i * n;
        float a0 = 0.f, a1 = 0.f, a2 = 0.f, a3 = 0.f;
        if (i != j) {
            const float* yi = ys + i * YSTR;
            const float* yj = ys + j * YSTR;
            #pragma unroll
            for (int q = 0; q < 32; q++) {
                float4 a = *(const float4*)(yi + q * 4);
                float4 b = *(const float4*)(yj + q * 4);
                a0 = fmaf(a.x, b.x, a0); a1 = fmaf(a.y, b.y, a1);
                a2 = fmaf(a.z, b.z, a2); a3 = fmaf(a.w, b.w, a3);
            }
        }
        S[i * CAP + j] = (a0 + a1) + (a2 + a3);
    }
    __syncthreads();

    // phase B: possum_i -> unsim_i
    const int warp = tid >> 5, lane = tid & 31;
    for (int i = warp; i < n; i += 8) {
        float ps = 0.f;
        for (int j = lane; j < n; j += 32)
            if (j != i) ps += __expf(S[i * CAP + j]);
        #pragma unroll
        for (int o = 16; o > 0; o >>= 1) ps += __shfl_xor_sync(0xffffffffu, ps, o);
        if (lane == 0) unsimS[i] = g_rowTot[gidx[i]] - ps;
    }
    __syncthreads();

    // phase C: loss terms
    float la = 0.f;
    for (int p = tid; p < nn; p += 256) {
        int i = p / n, j = p - i * n;
        if (i == j) continue;
        float s = S[i * CAP + j];
        la += logf(__expf(s) + unsimS[i]) - s;
    }
    tr[tid] = la;
    __syncthreads();
    #pragma unroll
    for (int o = 128; o > 0; o >>= 1) {
        if (tid < o) tr[tid] += tr[tid + o];
        __syncthreads();
    }
    if (tid == 0) { g_classLoss[c] = tr[0]; g_classN[c] = (float)n * (float)(n - 1); }
}

// ---------------- 8) finalize ----------------
__global__ void finalize_kernel(float* __restrict__ out) {
    __shared__ float sl[NCLS], sn[NCLS];
    int t = threadIdx.x;
    sl[t] = g_classLoss[t];
    sn[t] = g_classN[t];
    __syncthreads();
    if (t == 0) {
        float L = 0.f, P = 0.f;
        for (int k = 0; k < NCLS; k++) { L += sl[k]; P += sn[k]; }
        out[0] = L / P;
    }
}

// ---------------- launch ----------------
extern "C" void kernel_launch(void* const* d_in, const int* in_sizes, int n_in,
                              void* d_out, int out_size) {
    const float* x     = (const float*)d_in[0];
    const int*   label = (const int*)d_in[1];
    float*       out   = (float*)d_out;

    cudaFuncSetAttribute(gram_hmma, cudaFuncAttributeMaxDynamicSharedMemorySize, SM_TOTAL);
    cudaFuncSetAttribute(class_loss_kernel, cudaFuncAttributeMaxDynamicSharedMemorySize, CLS_SMEM);

    norms_kernel<<<N / 8, 256>>>(x);
    prep_kernel<<<N * 32 / 256, 256>>>(x);
    build_ofs_kernel<<<1, 256>>>(label);
    scatter_kernel<<<NCHUNK, 256>>>(label);
    gram_hmma<<<NT * NT, 256, SM_TOTAL>>>();
    rowtot_kernel<<<N / 256, 256>>>();
    class_loss_kernel<<<NCLS, 256, CLS_SMEM>>>();
    finalize_kernel<<<1, NCLS>>>(out);
}

// round 5
// speedup vs baseline: 6.7932x; 1.4713x over previous
#include <cuda_runtime.h>
#include <cuda_bf16.h>
#include <math.h>
#include <stdint.h>

#define N      8192
#define D      128
#define NCLS   128
#define NCHUNK 32            // N/256
#define TT     128           // gram tile (rows == cols)
#define NT     (N / TT)      // 64 tiles per dim
#define NTRI   (NT * (NT + 1) / 2)   // 2080 upper-triangular tiles
#define CAP    128           // max class size supported
#define YSTR   132           // padded row stride (floats) for class smem
#define LDAB   272           // bytes per smem tile row: 128 bf16 + 8 pad

// ---------------- scratch (device globals; no allocations) ----------------
__device__ float          g_invn[N];
__device__ float          g_y[N * D];          // prescaled: y = x * invn * sqrt(1/T)
__device__ __nv_bfloat16  g_yhi[N * D];
__device__ __nv_bfloat16  g_ylo[N * D];
__device__ float          g_rowPart[NT * N];   // per-coltile partial row sums of e
__device__ float          g_rowTot[N];
__device__ int            g_ofs[NCLS + 1];
__device__ int            g_chunkBase[NCHUNK][NCLS];
__device__ int            g_order[N];
__device__ float          g_classLoss[NCLS];
__device__ float          g_classN[NCLS];

// ---------------- helpers ----------------
__device__ __forceinline__ uint32_t smem_u32(const void* p) {
    uint32_t a;
    asm("{ .reg .u64 t; cvta.to.shared.u64 t, %1; cvt.u32.u64 %0, t; }" : "=r"(a) : "l"(p));
    return a;
}

#define LDSM4(r, addr)                                                           \
    asm volatile("ldmatrix.sync.aligned.m8n8.x4.shared.b16 {%0,%1,%2,%3}, [%4];" \
        : "=r"((r)[0]), "=r"((r)[1]), "=r"((r)[2]), "=r"((r)[3]) : "r"(addr))

#define MMA16816(d, a, b0r, b1r)                                                 \
    asm volatile("mma.sync.aligned.m16n8k16.row.col.f32.bf16.bf16.f32 "          \
        "{%0,%1,%2,%3}, {%4,%5,%6,%7}, {%8,%9}, {%0,%1,%2,%3};"                  \
        : "+f"((d)[0]), "+f"((d)[1]), "+f"((d)[2]), "+f"((d)[3])                 \
        : "r"((a)[0]), "r"((a)[1]), "r"((a)[2]), "r"((a)[3]), "r"(b0r), "r"(b1r))

// ---------------- 1) row norms ----------------
__global__ void norms_kernel(const float* __restrict__ x) {
    int row  = blockIdx.x * 8 + (threadIdx.x >> 5);
    int lane = threadIdx.x & 31;
    float4 v = *(const float4*)(x + row * D + lane * 4);
    float s = v.x * v.x + v.y * v.y + v.z * v.z + v.w * v.w;
    #pragma unroll
    for (int o = 16; o > 0; o >>= 1) s += __shfl_xor_sync(0xffffffffu, s, o);
    if (lane == 0) g_invn[row] = 1.0f / fmaxf(sqrtf(s), 1e-6f);
}

// ---------------- 2) prescale + bf16 hi/lo split ----------------
__global__ void prep_kernel(const float* __restrict__ x) {
    int i = blockIdx.x * 256 + threadIdx.x;   // float4 index
    int row = i >> 5;
    float s = g_invn[row] * 2.2360679774997896f;   // sqrt(1/T)
    float4 v = ((const float4*)x)[i];
    v.x *= s; v.y *= s; v.z *= s; v.w *= s;
    ((float4*)g_y)[i] = v;
    __nv_bfloat16 h0 = __float2bfloat16(v.x), h1 = __float2bfloat16(v.y);
    __nv_bfloat16 h2 = __float2bfloat16(v.z), h3 = __float2bfloat16(v.w);
    __nv_bfloat162* ph = (__nv_bfloat162*)g_yhi;
    __nv_bfloat162* pl = (__nv_bfloat162*)g_ylo;
    ph[i * 2 + 0] = __nv_bfloat162(h0, h1);
    ph[i * 2 + 1] = __nv_bfloat162(h2, h3);
    pl[i * 2 + 0] = __nv_bfloat162(__float2bfloat16(v.x - __bfloat162float(h0)),
                                   __float2bfloat16(v.y - __bfloat162float(h1)));
    pl[i * 2 + 1] = __nv_bfloat162(__float2bfloat16(v.z - __bfloat162float(h2)),
                                   __float2bfloat16(v.w - __bfloat162float(h3)));
}

// ---------------- 3) class offsets (deterministic) ----------------
__global__ void build_ofs_kernel(const int* __restrict__ label) {
    __shared__ int cnt[NCHUNK][NCLS];
    __shared__ int tot[NCLS];
    __shared__ int ofs[NCLS];
    int t = threadIdx.x;
    for (int i = t; i < NCHUNK * NCLS; i += 256) (&cnt[0][0])[i] = 0;
    __syncthreads();
    for (int i = t; i < N; i += 256) atomicAdd(&cnt[i >> 8][label[i]], 1);
    __syncthreads();
    if (t < NCLS) {
        int run = 0;
        #pragma unroll
        for (int k = 0; k < NCHUNK; k++) { int v = cnt[k][t]; cnt[k][t] = run; run += v; }
        tot[t] = run;
    }
    __syncthreads();
    if (t == 0) {
        int run = 0;
        for (int c = 0; c < NCLS; c++) { ofs[c] = run; g_ofs[c] = run; run += tot[c]; }
        g_ofs[NCLS] = run;
    }
    __syncthreads();
    if (t < NCLS)
        #pragma unroll
        for (int k = 0; k < NCHUNK; k++) g_chunkBase[k][t] = ofs[t] + cnt[k][t];
}

// ---------------- 4) stable scatter ----------------
__global__ void scatter_kernel(const int* __restrict__ label) {
    __shared__ unsigned char lab[256];
    int t = threadIdx.x;
    int gi = blockIdx.x * 256 + t;
    int c = label[gi];
    lab[t] = (unsigned char)c;
    __syncthreads();
    int rank = 0;
    for (int j = 0; j < t; j++) rank += (lab[j] == (unsigned char)c);
    g_order[g_chunkBase[blockIdx.x][c] + rank] = gi;
}

// ---------------- 5) HMMA Gram (upper-triangular) + exp + row/col sums ----------------
#define SM_AHI   0
#define SM_ALO   (128 * LDAB)
#define SM_BHI   (2 * 128 * LDAB)
#define SM_BLO   (3 * 128 * LDAB)
#define SM_TOTAL (4 * 128 * LDAB)     // 139264 B

__global__ void __launch_bounds__(256, 1) gram_hmma() {
    extern __shared__ char smem[];
    const uint32_t sb = smem_u32(smem);
    const int tid = threadIdx.x, wid = tid >> 5, lane = tid & 31;

    // triangular block -> (rt, ct), rt <= ct
    const int b = blockIdx.x;
    int rt = (int)((129.0f - sqrtf(16641.0f - 8.0f * (float)b)) * 0.5f);
    while (rt * NT - rt * (rt - 1) / 2 > b) rt--;
    while ((rt + 1) * NT - (rt + 1) * rt / 2 <= b) rt++;
    const int ct = rt + (b - (rt * NT - rt * (rt - 1) / 2));
    const int rowBase = rt * TT, colBase = ct * TT;
    const bool offDiag = (rt != ct);

    // stage tiles
    for (int i = tid; i < 128 * 16; i += 256) {
        int r = i >> 4, c8 = i & 15;
        uint32_t off = (uint32_t)r * LDAB + (uint32_t)c8 * 16;
        *(uint4*)(smem + SM_AHI + off) = ((const uint4*)(g_yhi + (size_t)(rowBase + r) * D))[c8];
        *(uint4*)(smem + SM_ALO + off) = ((const uint4*)(g_ylo + (size_t)(rowBase + r) * D))[c8];
        *(uint4*)(smem + SM_BHI + off) = ((const uint4*)(g_yhi + (size_t)(colBase + r) * D))[c8];
        *(uint4*)(smem + SM_BLO + off) = ((const uint4*)(g_ylo + (size_t)(colBase + r) * D))[c8];
    }
    __syncthreads();

    const int wy = wid & 3, wx = wid >> 2;      // warp grid 4(M) x 2(N)
    const int aRow = wy * 32, bRow = wx * 64;

    const int aR  = aRow + (lane & 15);
    const int aC  = (lane >> 4) * 16;
    const int bR  = bRow + (lane & 7) + ((lane >> 4) << 3);
    const int bC  = ((lane >> 3) & 1) * 16;

    float acc[2][8][4];
    #pragma unroll
    for (int mi = 0; mi < 2; mi++)
        #pragma unroll
        for (int nt = 0; nt < 8; nt++)
            #pragma unroll
            for (int q = 0; q < 4; q++) acc[mi][nt][q] = 0.f;

    #pragma unroll
    for (int kk = 0; kk < 8; kk++) {
        const uint32_t kOff = (uint32_t)kk * 32;
        uint32_t ah[2][4], al[2][4], bh[4][4], bl[4][4];
        #pragma unroll
        for (int mi = 0; mi < 2; mi++) {
            uint32_t ad = sb + (uint32_t)(aR + mi * 16) * LDAB + kOff + aC;
            LDSM4(ah[mi], ad + SM_AHI);
            LDSM4(al[mi], ad + SM_ALO);
        }
        #pragma unroll
        for (int ni = 0; ni < 4; ni++) {
            uint32_t bd = sb + (uint32_t)(bR + ni * 16) * LDAB + kOff + bC;
            LDSM4(bh[ni], bd + SM_BHI);
            LDSM4(bl[ni], bd + SM_BLO);
        }
        // product-major: 16 independent accumulators between reuses
        #pragma unroll
        for (int mi = 0; mi < 2; mi++)
            #pragma unroll
            for (int ni = 0; ni < 4; ni++)
                #pragma unroll
                for (int h = 0; h < 2; h++)
                    MMA16816(acc[mi][ni * 2 + h], ah[mi], bh[ni][h * 2], bh[ni][h * 2 + 1]);
        #pragma unroll
        for (int mi = 0; mi < 2; mi++)
            #pragma unroll
            for (int ni = 0; ni < 4; ni++)
                #pragma unroll
                for (int h = 0; h < 2; h++)
                    MMA16816(acc[mi][ni * 2 + h], ah[mi], bl[ni][h * 2], bl[ni][h * 2 + 1]);
        #pragma unroll
        for (int mi = 0; mi < 2; mi++)
            #pragma unroll
            for (int ni = 0; ni < 4; ni++)
                #pragma unroll
                for (int h = 0; h < 2; h++)
                    MMA16816(acc[mi][ni * 2 + h], al[mi], bh[ni][h * 2], bh[ni][h * 2 + 1]);
    }

    // epilogue: e = exp(acc), diag zeroed; row sums + (off-diag) column sums
    const int g = lane >> 2, t4 = lane & 3;
    float rsum[2][2] = {{0.f, 0.f}, {0.f, 0.f}};
    float cs[8][2];
    #pragma unroll
    for (int nt = 0; nt < 8; nt++) { cs[nt][0] = 0.f; cs[nt][1] = 0.f; }

    #pragma unroll
    for (int mi = 0; mi < 2; mi++) {
        const int row0 = rowBase + aRow + mi * 16 + g;
        const int row1 = row0 + 8;
        #pragma unroll
        for (int nt = 0; nt < 8; nt++) {
            const int gc = colBase + bRow + nt * 8 + t4 * 2;
            float e0 = (row0 == gc    ) ? 0.f : __expf(acc[mi][nt][0]);
            float e1 = (row0 == gc + 1) ? 0.f : __expf(acc[mi][nt][1]);
            float e2 = (row1 == gc    ) ? 0.f : __expf(acc[mi][nt][2]);
            float e3 = (row1 == gc + 1) ? 0.f : __expf(acc[mi][nt][3]);
            rsum[mi][0] += e0 + e1;
            rsum[mi][1] += e2 + e3;
            cs[nt][0] += e0 + e2;
            cs[nt][1] += e1 + e3;
        }
    }
    __syncthreads();                               // tiles no longer needed
    float* red    = (float*)smem;                  // [128][2 wx]
    float* colRed = (float*)(smem + 1024);         // [128][4 wy]

    #pragma unroll
    for (int mi = 0; mi < 2; mi++)
        #pragma unroll
        for (int hrow = 0; hrow < 2; hrow++) {
            float s = rsum[mi][hrow];
            s += __shfl_xor_sync(0xffffffffu, s, 1);
            s += __shfl_xor_sync(0xffffffffu, s, 2);
            if (t4 == 0) red[(aRow + mi * 16 + hrow * 8 + g) * 2 + wx] = s;
        }

    if (offDiag) {
        #pragma unroll
        for (int nt = 0; nt < 8; nt++)
            #pragma unroll
            for (int sc = 0; sc < 2; sc++) {
                float s = cs[nt][sc];
                s += __shfl_xor_sync(0xffffffffu, s, 4);
                s += __shfl_xor_sync(0xffffffffu, s, 8);
                s += __shfl_xor_sync(0xffffffffu, s, 16);
                if (g == 0) colRed[(bRow + nt * 8 + t4 * 2 + sc) * 4 + wy] = s;
            }
    }
    __syncthreads();
    if (tid < 128) {
        g_rowPart[(size_t)ct * N + rowBase + tid] = red[tid * 2] + red[tid * 2 + 1];
        if (offDiag)
            g_rowPart[(size_t)rt * N + colBase + tid] =
                (colRed[tid * 4] + colRed[tid * 4 + 1]) + (colRed[tid * 4 + 2] + colRed[tid * 4 + 3]);
    }
}

// ---------------- 6) row totals (fixed order, deterministic) ----------------
__global__ void rowtot_kernel() {
    int r = blockIdx.x * 256 + threadIdx.x;
    float s = 0.f;
    #pragma unroll
    for (int c = 0; c < NT; c++) s += g_rowPart[(size_t)c * N + r];
    g_rowTot[r] = s;
}

// ---------------- 7) per-class loss ----------------
#define CLS_SMEM (CAP * YSTR * 4 + CAP * CAP * 4)
__global__ void __launch_bounds__(256, 1) class_loss_kernel() {
    extern __shared__ char cs_[];
    float* ys = (float*)cs_;
    float* S  = (float*)(cs_ + CAP * YSTR * 4);
    __shared__ int   gidx[CAP];
    __shared__ float unsimS[CAP];
    __shared__ float tr[256];
    const int c = blockIdx.x, tid = threadIdx.x;
    const int base = g_ofs[c];
    int n = g_ofs[c + 1] - base;
    if (n > CAP) n = CAP;

    for (int i = tid; i < n; i += 256) gidx[i] = g_order[base + i];
    __syncthreads();
    for (int i = tid; i < n * 32; i += 256) {
        int m = i >> 5, q = i & 31;
        *(float4*)(ys + m * YSTR + q * 4) = ((const float4*)(g_y + (size_t)gidx[m] * D))[q];
    }
    __syncthreads();

    const int nn = n * n;
    for (int p = tid; p < nn; p += 256) {
        int i = p / n, j = p - i * n;
        float a0 = 0.f, a1 = 0.f, a2 = 0.f, a3 = 0.f;
        if (i != j) {
            const float* yi = ys + i * YSTR;
            const float* yj = ys + j * YSTR;
            #pragma unroll
            for (int q = 0; q < 32; q++) {
                float4 a = *(const float4*)(yi + q * 4);
                float4 b = *(const float4*)(yj + q * 4);
                a0 = fmaf(a.x, b.x, a0); a1 = fmaf(a.y, b.y, a1);
                a2 = fmaf(a.z, b.z, a2); a3 = fmaf(a.w, b.w, a3);
            }
        }
        S[i * CAP + j] = (a0 + a1) + (a2 + a3);
    }
    __syncthreads();

    const int warp = tid >> 5, lane = tid & 31;
    for (int i = warp; i < n; i += 8) {
        float ps = 0.f;
        for (int j = lane; j < n; j += 32)
            if (j != i) ps += __expf(S[i * CAP + j]);
        #pragma unroll
        for (int o = 16; o > 0; o >>= 1) ps += __shfl_xor_sync(0xffffffffu, ps, o);
        if (lane == 0) unsimS[i] = g_rowTot[gidx[i]] - ps;
    }
    __syncthreads();

    float la = 0.f;
    for (int p = tid; p < nn; p += 256) {
        int i = p / n, j = p - i * n;
        if (i == j) continue;
        float s = S[i * CAP + j];
        la += logf(__expf(s) + unsimS[i]) - s;
    }
    tr[tid] = la;
    __syncthreads();
    #pragma unroll
    for (int o = 128; o > 0; o >>= 1) {
        if (tid < o) tr[tid] += tr[tid + o];
        __syncthreads();
    }
    if (tid == 0) { g_classLoss[c] = tr[0]; g_classN[c] = (float)n * (float)(n - 1); }
}

// ---------------- 8) finalize ----------------
__global__ void finalize_kernel(float* __restrict__ out) {
    __shared__ float sl[NCLS], sn[NCLS];
    int t = threadIdx.x;
    sl[t] = g_classLoss[t];
    sn[t] = g_classN[t];
    __syncthreads();
    if (t == 0) {
        float L = 0.f, P = 0.f;
        for (int k = 0; k < NCLS; k++) { L += sl[k]; P += sn[k]; }
        out[0] = L / P;
    }
}

// ---------------- launch ----------------
extern "C" void kernel_launch(void* const* d_in, const int* in_sizes, int n_in,
                              void* d_out, int out_size) {
    const float* x     = (const float*)d_in[0];
    const int*   label = (const int*)d_in[1];
    float*       out   = (float*)d_out;

    cudaFuncSetAttribute(gram_hmma, cudaFuncAttributeMaxDynamicSharedMemorySize, SM_TOTAL);
    cudaFuncSetAttribute(class_loss_kernel, cudaFuncAttributeMaxDynamicSharedMemorySize, CLS_SMEM);

    norms_kernel<<<N / 8, 256>>>(x);
    prep_kernel<<<N * 32 / 256, 256>>>(x);
    build_ofs_kernel<<<1, 256>>>(label);
    scatter_kernel<<<NCHUNK, 256>>>(label);
    gram_hmma<<<NTRI, 256, SM_TOTAL>>>();
    rowtot_kernel<<<N / 256, 256>>>();
    class_loss_kernel<<<NCLS, 256, CLS_SMEM>>>();
    finalize_kernel<<<1, NCLS>>>(out);
}

// round 6
// speedup vs baseline: 14.7124x; 2.1658x over previous
#include <cuda_runtime.h>
#include <cuda_bf16.h>
#include <math.h>
#include <stdint.h>

#define N      8192
#define D      128
#define NCLS   128
#define NCHUNK 32            // N/256
#define TT     128           // gram tile (rows == cols)
#define NT     (N / TT)      // 64 tiles per dim
#define NTRI   (NT * (NT + 1) / 2)   // 2080 upper-triangular tiles
#define CAP    128           // max class size supported
#define LDAB   272           // bytes per smem tile row: 128 bf16 + 8 pad
#define SSTR   132           // S matrix row stride (floats)

// ---------------- scratch (device globals; no allocations) ----------------
__device__ __nv_bfloat16  g_yhi[N * D];        // bf16(x * invn * sqrt(1/T))
__device__ float          g_rowPart[NT * N];   // per-coltile partial row sums of e
__device__ float          g_rowTot[N];
__device__ int            g_ofs[NCLS + 1];
__device__ int            g_chunkBase[NCHUNK][NCLS];
__device__ int            g_order[N];
__device__ float          g_classLoss[NCLS];
__device__ float          g_classN[NCLS];

// ---------------- helpers ----------------
__device__ __forceinline__ uint32_t smem_u32(const void* p) {
    uint32_t a;
    asm("{ .reg .u64 t; cvta.to.shared.u64 t, %1; cvt.u32.u64 %0, t; }" : "=r"(a) : "l"(p));
    return a;
}

#define LDSM4(r, addr)                                                           \
    asm volatile("ldmatrix.sync.aligned.m8n8.x4.shared.b16 {%0,%1,%2,%3}, [%4];" \
        : "=r"((r)[0]), "=r"((r)[1]), "=r"((r)[2]), "=r"((r)[3]) : "r"(addr))

#define MMA16816(d, a, b0r, b1r)                                                 \
    asm volatile("mma.sync.aligned.m16n8k16.row.col.f32.bf16.bf16.f32 "          \
        "{%0,%1,%2,%3}, {%4,%5,%6,%7}, {%8,%9}, {%0,%1,%2,%3};"                  \
        : "+f"((d)[0]), "+f"((d)[1]), "+f"((d)[2]), "+f"((d)[3])                 \
        : "r"((a)[0]), "r"((a)[1]), "r"((a)[2]), "r"((a)[3]), "r"(b0r), "r"(b1r))

// ---------------- 1) fused norms + prescale + bf16 ----------------
__global__ void prep_kernel(const float* __restrict__ x) {
    int row  = blockIdx.x * 8 + (threadIdx.x >> 5);
    int lane = threadIdx.x & 31;
    float4 v = *(const float4*)(x + (size_t)row * D + lane * 4);
    float ss = v.x * v.x + v.y * v.y + v.z * v.z + v.w * v.w;
    #pragma unroll
    for (int o = 16; o > 0; o >>= 1) ss += __shfl_xor_sync(0xffffffffu, ss, o);
    float s = rsqrtf(fmaxf(ss, 1e-12f)) * 2.2360679774997896f;   // invnorm * sqrt(1/T)
    __nv_bfloat162 p0(__float2bfloat16(v.x * s), __float2bfloat16(v.y * s));
    __nv_bfloat162 p1(__float2bfloat16(v.z * s), __float2bfloat16(v.w * s));
    uint2 pk;
    pk.x = *(uint32_t*)&p0;
    pk.y = *(uint32_t*)&p1;
    *(uint2*)(g_yhi + (size_t)row * D + lane * 4) = pk;
}

// ---------------- 2) class offsets (deterministic) ----------------
__global__ void build_ofs_kernel(const int* __restrict__ label) {
    __shared__ int cnt[NCHUNK][NCLS];
    __shared__ int tot[NCLS];
    __shared__ int ofs[NCLS];
    int t = threadIdx.x;
    for (int i = t; i < NCHUNK * NCLS; i += 256) (&cnt[0][0])[i] = 0;
    __syncthreads();
    for (int i = t; i < N; i += 256) atomicAdd(&cnt[i >> 8][label[i]], 1);
    __syncthreads();
    if (t < NCLS) {
        int run = 0;
        #pragma unroll
        for (int k = 0; k < NCHUNK; k++) { int v = cnt[k][t]; cnt[k][t] = run; run += v; }
        tot[t] = run;
    }
    __syncthreads();
    if (t == 0) {
        int run = 0;
        for (int c = 0; c < NCLS; c++) { ofs[c] = run; g_ofs[c] = run; run += tot[c]; }
        g_ofs[NCLS] = run;
    }
    __syncthreads();
    if (t < NCLS)
        #pragma unroll
        for (int k = 0; k < NCHUNK; k++) g_chunkBase[k][t] = ofs[t] + cnt[k][t];
}

// ---------------- 3) stable scatter (ballot rank) ----------------
__global__ void scatter_kernel(const int* __restrict__ label) {
    __shared__ int wcnt[8][NCLS];
    const int t = threadIdx.x, w = t >> 5, lane = t & 31;
    for (int i = t; i < 8 * NCLS; i += 256) (&wcnt[0][0])[i] = 0;
    __syncthreads();
    const int gi = blockIdx.x * 256 + t;
    const int c = label[gi];
    unsigned mask = __match_any_sync(0xffffffffu, c);
    int rankInWarp = __popc(mask & ((1u << lane) - 1u));
    if (lane == (__ffs(mask) - 1)) wcnt[w][c] = __popc(mask);
    __syncthreads();
    int before = 0;
    for (int w2 = 0; w2 < w; w2++) before += wcnt[w2][c];
    g_order[g_chunkBase[blockIdx.x][c] + before + rankInWarp] = gi;
}

// ---------------- 4) HMMA Gram (upper-triangular, bf16) + exp + row/col sums ----------------
#define SM_AHI   0
#define SM_BHI   (128 * LDAB)
#define SM_TOTAL (2 * 128 * LDAB)     // 69632 B -> 2 CTAs/SM

__global__ void __launch_bounds__(256, 2) gram_hmma() {
    extern __shared__ char smem[];
    const uint32_t sb = smem_u32(smem);
    const int tid = threadIdx.x, wid = tid >> 5, lane = tid & 31;

    // triangular block -> (rt, ct), rt <= ct
    const int b = blockIdx.x;
    int rt = (int)((129.0f - sqrtf(16641.0f - 8.0f * (float)b)) * 0.5f);
    while (rt * NT - rt * (rt - 1) / 2 > b) rt--;
    while ((rt + 1) * NT - (rt + 1) * rt / 2 <= b) rt++;
    const int ct = rt + (b - (rt * NT - rt * (rt - 1) / 2));
    const int rowBase = rt * TT, colBase = ct * TT;
    const bool offDiag = (rt != ct);

    // stage tiles (B only when off-diagonal; diag reuses A)
    for (int i = tid; i < 128 * 16; i += 256) {
        int r = i >> 4, c8 = i & 15;
        uint32_t off = (uint32_t)r * LDAB + (uint32_t)c8 * 16;
        *(uint4*)(smem + SM_AHI + off) = ((const uint4*)(g_yhi + (size_t)(rowBase + r) * D))[c8];
        if (offDiag)
            *(uint4*)(smem + SM_BHI + off) = ((const uint4*)(g_yhi + (size_t)(colBase + r) * D))[c8];
    }
    __syncthreads();

    const uint32_t bTile = offDiag ? SM_BHI : SM_AHI;
    const int wy = wid & 3, wx = wid >> 2;      // warp grid 4(M) x 2(N)
    const int aRow = wy * 32, bRow = wx * 64;

    const int aR  = aRow + (lane & 15);
    const int aC  = (lane >> 4) * 16;
    const int bR  = bRow + (lane & 7) + ((lane >> 4) << 3);
    const int bC  = ((lane >> 3) & 1) * 16;

    float acc[2][8][4];
    #pragma unroll
    for (int mi = 0; mi < 2; mi++)
        #pragma unroll
        for (int nt = 0; nt < 8; nt++)
            #pragma unroll
            for (int q = 0; q < 4; q++) acc[mi][nt][q] = 0.f;

    #pragma unroll
    for (int kk = 0; kk < 8; kk++) {
        const uint32_t kOff = (uint32_t)kk * 32;
        uint32_t ah[2][4], bh[4][4];
        #pragma unroll
        for (int mi = 0; mi < 2; mi++) {
            uint32_t ad = sb + SM_AHI + (uint32_t)(aR + mi * 16) * LDAB + kOff + aC;
            LDSM4(ah[mi], ad);
        }
        #pragma unroll
        for (int ni = 0; ni < 4; ni++) {
            uint32_t bd = sb + bTile + (uint32_t)(bR + ni * 16) * LDAB + kOff + bC;
            LDSM4(bh[ni], bd);
        }
        #pragma unroll
        for (int mi = 0; mi < 2; mi++)
            #pragma unroll
            for (int ni = 0; ni < 4; ni++)
                #pragma unroll
                for (int h = 0; h < 2; h++)
                    MMA16816(acc[mi][ni * 2 + h], ah[mi], bh[ni][h * 2], bh[ni][h * 2 + 1]);
    }

    // epilogue: e = exp(acc), diag zeroed; row sums + (off-diag) column sums
    const int g = lane >> 2, t4 = lane & 3;
    float rsum[2][2] = {{0.f, 0.f}, {0.f, 0.f}};
    float cs[8][2];
    #pragma unroll
    for (int nt = 0; nt < 8; nt++) { cs[nt][0] = 0.f; cs[nt][1] = 0.f; }

    #pragma unroll
    for (int mi = 0; mi < 2; mi++) {
        const int row0 = rowBase + aRow + mi * 16 + g;
        const int row1 = row0 + 8;
        #pragma unroll
        for (int nt = 0; nt < 8; nt++) {
            const int gc = colBase + bRow + nt * 8 + t4 * 2;
            float e0 = (row0 == gc    ) ? 0.f : __expf(acc[mi][nt][0]);
            float e1 = (row0 == gc + 1) ? 0.f : __expf(acc[mi][nt][1]);
            float e2 = (row1 == gc    ) ? 0.f : __expf(acc[mi][nt][2]);
            float e3 = (row1 == gc + 1) ? 0.f : __expf(acc[mi][nt][3]);
            rsum[mi][0] += e0 + e1;
            rsum[mi][1] += e2 + e3;
            cs[nt][0] += e0 + e2;
            cs[nt][1] += e1 + e3;
        }
    }
    __syncthreads();                               // tiles no longer needed
    float* red    = (float*)smem;                  // [128][2 wx]
    float* colRed = (float*)(smem + 1024);         // [128][4 wy]

    #pragma unroll
    for (int mi = 0; mi < 2; mi++)
        #pragma unroll
        for (int hrow = 0; hrow < 2; hrow++) {
            float s = rsum[mi][hrow];
            s += __shfl_xor_sync(0xffffffffu, s, 1);
            s += __shfl_xor_sync(0xffffffffu, s, 2);
            if (t4 == 0) red[(aRow + mi * 16 + hrow * 8 + g) * 2 + wx] = s;
        }

    if (offDiag) {
        #pragma unroll
        for (int nt = 0; nt < 8; nt++)
            #pragma unroll
            for (int sc = 0; sc < 2; sc++) {
                float s = cs[nt][sc];
                s += __shfl_xor_sync(0xffffffffu, s, 4);
                s += __shfl_xor_sync(0xffffffffu, s, 8);
                s += __shfl_xor_sync(0xffffffffu, s, 16);
                if (g == 0) colRed[(bRow + nt * 8 + t4 * 2 + sc) * 4 + wy] = s;
            }
    }
    __syncthreads();
    if (tid < 128) {
        g_rowPart[(size_t)ct * N + rowBase + tid] = red[tid * 2] + red[tid * 2 + 1];
        if (offDiag)
            g_rowPart[(size_t)rt * N + colBase + tid] =
                (colRed[tid * 4] + colRed[tid * 4 + 1]) + (colRed[tid * 4 + 2] + colRed[tid * 4 + 3]);
    }
}

// ---------------- 5) row totals (fixed order, deterministic) ----------------
__global__ void rowtot_kernel() {
    int r = blockIdx.x * 256 + threadIdx.x;
    float s = 0.f;
    #pragma unroll
    for (int c = 0; c < NT; c++) s += g_rowPart[(size_t)c * N + r];
    g_rowTot[r] = s;
}

// ---------------- 6) per-class loss: HMMA mini-Gram + loss terms ----------------
// dynamic smem: tile (128 x LDAB bytes) + S (128 x SSTR floats)
#define CLS_SMEM (128 * LDAB + 128 * SSTR * 4)
__global__ void __launch_bounds__(256, 1) class_loss_kernel() {
    extern __shared__ char cs_[];
    char*  tile = cs_;
    float* S    = (float*)(cs_ + 128 * LDAB);
    __shared__ int   gidx[CAP];
    __shared__ float unsimS[CAP];
    __shared__ float tr[256];
    const uint32_t sb = smem_u32(tile);
    const int c = blockIdx.x, tid = threadIdx.x, wid = tid >> 5, lane = tid & 31;
    const int base = g_ofs[c];
    int n = g_ofs[c + 1] - base;
    if (n > CAP) n = CAP;

    for (int i = tid; i < CAP; i += 256) gidx[i] = (i < n) ? g_order[base + i] : 0;
    __syncthreads();
    // stage class rows (bf16), zero-pad beyond n
    for (int i = tid; i < 128 * 16; i += 256) {
        int r = i >> 4, c8 = i & 15;
        uint32_t off = (uint32_t)r * LDAB + (uint32_t)c8 * 16;
        uint4 v = make_uint4(0u, 0u, 0u, 0u);
        if (r < n) v = ((const uint4*)(g_yhi + (size_t)gidx[r] * D))[c8];
        *(uint4*)(tile + off) = v;
    }
    __syncthreads();

    // mini-Gram: same 128x128x128 HMMA structure, A = B = tile
    const int wy = wid & 3, wx = wid >> 2;
    const int aRow = wy * 32, bRow = wx * 64;
    const int aR  = aRow + (lane & 15);
    const int aC  = (lane >> 4) * 16;
    const int bR  = bRow + (lane & 7) + ((lane >> 4) << 3);
    const int bC  = ((lane >> 3) & 1) * 16;

    float acc[2][8][4];
    #pragma unroll
    for (int mi = 0; mi < 2; mi++)
        #pragma unroll
        for (int nt = 0; nt < 8; nt++)
            #pragma unroll
            for (int q = 0; q < 4; q++) acc[mi][nt][q] = 0.f;

    #pragma unroll
    for (int kk = 0; kk < 8; kk++) {
        const uint32_t kOff = (uint32_t)kk * 32;
        uint32_t ah[2][4], bh[4][4];
        #pragma unroll
        for (int mi = 0; mi < 2; mi++)
            LDSM4(ah[mi], sb + (uint32_t)(aR + mi * 16) * LDAB + kOff + aC);
        #pragma unroll
        for (int ni = 0; ni < 4; ni++)
            LDSM4(bh[ni], sb + (uint32_t)(bR + ni * 16) * LDAB + kOff + bC);
        #pragma unroll
        for (int mi = 0; mi < 2; mi++)
            #pragma unroll
            for (int ni = 0; ni < 4; ni++)
                #pragma unroll
                for (int h = 0; h < 2; h++)
                    MMA16816(acc[mi][ni * 2 + h], ah[mi], bh[ni][h * 2], bh[ni][h * 2 + 1]);
    }

    // store S (s = sim/T)
    const int g = lane >> 2, t4 = lane & 3;
    #pragma unroll
    for (int mi = 0; mi < 2; mi++) {
        const int r0 = aRow + mi * 16 + g;
        #pragma unroll
        for (int nt = 0; nt < 8; nt++) {
            const int col = bRow + nt * 8 + t4 * 2;
            *(float2*)&S[r0 * SSTR + col]       = make_float2(acc[mi][nt][0], acc[mi][nt][1]);
            *(float2*)&S[(r0 + 8) * SSTR + col] = make_float2(acc[mi][nt][2], acc[mi][nt][3]);
        }
    }
    __syncthreads();

    // possum_i -> unsim_i
    for (int i = wid; i < n; i += 8) {
        float ps = 0.f;
        for (int j = lane; j < n; j += 32)
            if (j != i) ps += __expf(S[i * SSTR + j]);
        #pragma unroll
        for (int o = 16; o > 0; o >>= 1) ps += __shfl_xor_sync(0xffffffffu, ps, o);
        if (lane == 0) unsimS[i] = g_rowTot[gidx[i]] - ps;
    }
    __syncthreads();

    // loss terms
    float la = 0.f;
    const int nn = n * n;
    for (int p = tid; p < nn; p += 256) {
        int i = p / n, j = p - i * n;
        if (i == j) continue;
        float s = S[i * SSTR + j];
        la += __logf(__expf(s) + unsimS[i]) - s;
    }
    tr[tid] = la;
    __syncthreads();
    #pragma unroll
    for (int o = 128; o > 0; o >>= 1) {
        if (tid < o) tr[tid] += tr[tid + o];
        __syncthreads();
    }
    if (tid == 0) { g_classLoss[c] = tr[0]; g_classN[c] = (float)n * (float)(n - 1); }
}

// ---------------- 7) finalize ----------------
__global__ void finalize_kernel(float* __restrict__ out) {
    __shared__ float sl[NCLS], sn[NCLS];
    int t = threadIdx.x;
    sl[t] = g_classLoss[t];
    sn[t] = g_classN[t];
    __syncthreads();
    if (t == 0) {
        float L = 0.f, P = 0.f;
        for (int k = 0; k < NCLS; k++) { L += sl[k]; P += sn[k]; }
        out[0] = L / P;
    }
}

// ---------------- launch ----------------
extern "C" void kernel_launch(void* const* d_in, const int* in_sizes, int n_in,
                              void* d_out, int out_size) {
    const float* x     = (const float*)d_in[0];
    const int*   label = (const int*)d_in[1];
    float*       out   = (float*)d_out;

    cudaFuncSetAttribute(gram_hmma, cudaFuncAttributeMaxDynamicSharedMemorySize, SM_TOTAL);
    cudaFuncSetAttribute(class_loss_kernel, cudaFuncAttributeMaxDynamicSharedMemorySize, CLS_SMEM);

    prep_kernel<<<N / 8, 256>>>(x);
    build_ofs_kernel<<<1, 256>>>(label);
    scatter_kernel<<<NCHUNK, 256>>>(label);
    gram_hmma<<<NTRI, 256, SM_TOTAL>>>();
    rowtot_kernel<<<N / 256, 256>>>();
    class_loss_kernel<<<NCLS, 256, CLS_SMEM>>>();
    finalize_kernel<<<1, NCLS>>>(out);
}

// round 7
// speedup vs baseline: 16.8354x; 1.1443x over previous
#include <cuda_runtime.h>
#include <cuda_bf16.h>
#include <math.h>
#include <stdint.h>

#define N      8192
#define D      128
#define NCLS   128
#define NCHUNK 32            // N/256
#define TT     128           // gram tile (rows == cols)
#define NT     (N / TT)      // 64 tiles per dim
#define NTRI   (NT * (NT + 1) / 2)   // 2080 upper-triangular tiles
#define CAP    128           // max class size supported
#define LDAB   272           // bytes per smem tile row: 128 bf16 + 8 pad
#define SSTR   132           // S matrix row stride (floats)
#define LN2F   0.6931471805599453f

// ---------------- scratch (device globals; no allocations) ----------------
__device__ __nv_bfloat16  g_yhi[N * D];        // bf16(x * invn * sqrt(log2e/T))
__device__ float          g_rowPart[NT * N];   // per-coltile partial row sums of e
__device__ float          g_rowTot[N];
__device__ int            g_ofs[NCLS + 1];
__device__ int            g_chunkBase[NCHUNK][NCLS];
__device__ int            g_order[N];
__device__ float          g_classLoss[NCLS];
__device__ float          g_classN[NCLS];

// ---------------- helpers ----------------
__device__ __forceinline__ uint32_t smem_u32(const void* p) {
    uint32_t a;
    asm("{ .reg .u64 t; cvta.to.shared.u64 t, %1; cvt.u32.u64 %0, t; }" : "=r"(a) : "l"(p));
    return a;
}
__device__ __forceinline__ float ex2f(float x) {
    float r;
    asm("ex2.approx.ftz.f32 %0, %1;" : "=f"(r) : "f"(x));
    return r;
}
__device__ __forceinline__ float lg2f(float x) {
    float r;
    asm("lg2.approx.f32 %0, %1;" : "=f"(r) : "f"(x));
    return r;
}
__device__ __forceinline__ void cpa16(uint32_t dst, const void* src) {
    asm volatile("{ .reg .u64 g; cvta.to.global.u64 g, %1; cp.async.cg.shared.global [%0], [g], 16; }"
                 :: "r"(dst), "l"(src) : "memory");
}
#define CPA_WAIT() asm volatile("cp.async.commit_group;\n\tcp.async.wait_group 0;" ::: "memory")

#define LDSM4(r, addr)                                                           \
    asm volatile("ldmatrix.sync.aligned.m8n8.x4.shared.b16 {%0,%1,%2,%3}, [%4];" \
        : "=r"((r)[0]), "=r"((r)[1]), "=r"((r)[2]), "=r"((r)[3]) : "r"(addr))

#define MMA16816(d, a, b0r, b1r)                                                 \
    asm volatile("mma.sync.aligned.m16n8k16.row.col.f32.bf16.bf16.f32 "          \
        "{%0,%1,%2,%3}, {%4,%5,%6,%7}, {%8,%9}, {%0,%1,%2,%3};"                  \
        : "+f"((d)[0]), "+f"((d)[1]), "+f"((d)[2]), "+f"((d)[3])                 \
        : "r"((a)[0]), "r"((a)[1]), "r"((a)[2]), "r"((a)[3]), "r"(b0r), "r"(b1r))

// ---------------- 1) fused norms + prescale + bf16 (log2 domain) ----------------
__global__ void prep_kernel(const float* __restrict__ x) {
    int row  = blockIdx.x * 8 + (threadIdx.x >> 5);
    int lane = threadIdx.x & 31;
    float4 v = *(const float4*)(x + (size_t)row * D + lane * 4);
    float ss = v.x * v.x + v.y * v.y + v.z * v.z + v.w * v.w;
    #pragma unroll
    for (int o = 16; o > 0; o >>= 1) ss += __shfl_xor_sync(0xffffffffu, ss, o);
    // invnorm * sqrt(log2e / T) = invnorm * sqrt(5 * 1.4426950408889634)
    float s = rsqrtf(fmaxf(ss, 1e-12f)) * 2.6858190963521055f;
    __nv_bfloat162 p0(__float2bfloat16(v.x * s), __float2bfloat16(v.y * s));
    __nv_bfloat162 p1(__float2bfloat16(v.z * s), __float2bfloat16(v.w * s));
    uint2 pk;
    pk.x = *(uint32_t*)&p0;
    pk.y = *(uint32_t*)&p1;
    *(uint2*)(g_yhi + (size_t)row * D + lane * 4) = pk;
}

// ---------------- 2) class offsets (deterministic) ----------------
__global__ void build_ofs_kernel(const int* __restrict__ label) {
    __shared__ int cnt[NCHUNK][NCLS];
    __shared__ int tot[NCLS];
    __shared__ int ofs[NCLS];
    int t = threadIdx.x;
    for (int i = t; i < NCHUNK * NCLS; i += 256) (&cnt[0][0])[i] = 0;
    __syncthreads();
    for (int i = t; i < N; i += 256) atomicAdd(&cnt[i >> 8][label[i]], 1);
    __syncthreads();
    if (t < NCLS) {
        int run = 0;
        #pragma unroll
        for (int k = 0; k < NCHUNK; k++) { int v = cnt[k][t]; cnt[k][t] = run; run += v; }
        tot[t] = run;
    }
    __syncthreads();
    if (t == 0) {
        int run = 0;
        for (int c = 0; c < NCLS; c++) { ofs[c] = run; g_ofs[c] = run; run += tot[c]; }
        g_ofs[NCLS] = run;
    }
    __syncthreads();
    if (t < NCLS)
        #pragma unroll
        for (int k = 0; k < NCHUNK; k++) g_chunkBase[k][t] = ofs[t] + cnt[k][t];
}

// ---------------- 3) stable scatter (ballot rank) ----------------
__global__ void scatter_kernel(const int* __restrict__ label) {
    __shared__ int wcnt[8][NCLS];
    const int t = threadIdx.x, w = t >> 5, lane = t & 31;
    for (int i = t; i < 8 * NCLS; i += 256) (&wcnt[0][0])[i] = 0;
    __syncthreads();
    const int gi = blockIdx.x * 256 + t;
    const int c = label[gi];
    unsigned mask = __match_any_sync(0xffffffffu, c);
    int rankInWarp = __popc(mask & ((1u << lane) - 1u));
    if (lane == (__ffs(mask) - 1)) wcnt[w][c] = __popc(mask);
    __syncthreads();
    int before = 0;
    for (int w2 = 0; w2 < w; w2++) before += wcnt[w2][c];
    g_order[g_chunkBase[blockIdx.x][c] + before + rankInWarp] = gi;
}

// ---------------- 4) HMMA Gram (upper-triangular, bf16) + exp2 + row/col sums ----------------
#define SM_AHI   0
#define SM_BHI   (128 * LDAB)
#define SM_TOTAL (2 * 128 * LDAB)     // 69632 B -> 2 CTAs/SM

__global__ void __launch_bounds__(256, 2) gram_hmma() {
    extern __shared__ char smem[];
    const uint32_t sb = smem_u32(smem);
    const int tid = threadIdx.x, wid = tid >> 5, lane = tid & 31;

    // triangular block -> (rt, ct), rt <= ct
    const int b = blockIdx.x;
    int rt = (int)((129.0f - sqrtf(16641.0f - 8.0f * (float)b)) * 0.5f);
    while (rt * NT - rt * (rt - 1) / 2 > b) rt--;
    while ((rt + 1) * NT - (rt + 1) * rt / 2 <= b) rt++;
    const int ct = rt + (b - (rt * NT - rt * (rt - 1) / 2));
    const int rowBase = rt * TT, colBase = ct * TT;
    const bool offDiag = (rt != ct);

    // stage tiles via cp.async (B only when off-diagonal; diag reuses A)
    for (int i = tid; i < 128 * 16; i += 256) {
        int r = i >> 4, c8 = i & 15;
        uint32_t off = (uint32_t)r * LDAB + (uint32_t)c8 * 16;
        cpa16(sb + SM_AHI + off, g_yhi + (size_t)(rowBase + r) * D + c8 * 8);
        if (offDiag)
            cpa16(sb + SM_BHI + off, g_yhi + (size_t)(colBase + r) * D + c8 * 8);
    }
    CPA_WAIT();
    __syncthreads();

    const uint32_t bTile = offDiag ? SM_BHI : SM_AHI;
    const int wy = wid & 3, wx = wid >> 2;      // warp grid 4(M) x 2(N)
    const int aRow = wy * 32, bRow = wx * 64;

    const int aR  = aRow + (lane & 15);
    const int aC  = (lane >> 4) * 16;
    const int bR  = bRow + (lane & 7) + ((lane >> 4) << 3);
    const int bC  = ((lane >> 3) & 1) * 16;

    float acc[2][8][4];
    #pragma unroll
    for (int mi = 0; mi < 2; mi++)
        #pragma unroll
        for (int nt = 0; nt < 8; nt++)
            #pragma unroll
            for (int q = 0; q < 4; q++) acc[mi][nt][q] = 0.f;

    #pragma unroll
    for (int kk = 0; kk < 8; kk++) {
        const uint32_t kOff = (uint32_t)kk * 32;
        uint32_t ah[2][4], bh[4][4];
        #pragma unroll
        for (int mi = 0; mi < 2; mi++)
            LDSM4(ah[mi], sb + SM_AHI + (uint32_t)(aR + mi * 16) * LDAB + kOff + aC);
        #pragma unroll
        for (int ni = 0; ni < 4; ni++)
            LDSM4(bh[ni], sb + bTile + (uint32_t)(bR + ni * 16) * LDAB + kOff + bC);
        #pragma unroll
        for (int mi = 0; mi < 2; mi++)
            #pragma unroll
            for (int ni = 0; ni < 4; ni++)
                #pragma unroll
                for (int h = 0; h < 2; h++)
                    MMA16816(acc[mi][ni * 2 + h], ah[mi], bh[ni][h * 2], bh[ni][h * 2 + 1]);
    }

    // epilogue: e = exp2(acc); branch-specialized (diag checks only when rt==ct)
    const int g = lane >> 2, t4 = lane & 3;
    float rsum[2][2] = {{0.f, 0.f}, {0.f, 0.f}};
    float cs[8][2];
    #pragma unroll
    for (int nt = 0; nt < 8; nt++) { cs[nt][0] = 0.f; cs[nt][1] = 0.f; }

    if (offDiag) {
        #pragma unroll
        for (int mi = 0; mi < 2; mi++)
            #pragma unroll
            for (int nt = 0; nt < 8; nt++) {
                float e0 = ex2f(acc[mi][nt][0]);
                float e1 = ex2f(acc[mi][nt][1]);
                float e2 = ex2f(acc[mi][nt][2]);
                float e3 = ex2f(acc[mi][nt][3]);
                rsum[mi][0] += e0 + e1;
                rsum[mi][1] += e2 + e3;
                cs[nt][0] += e0 + e2;
                cs[nt][1] += e1 + e3;
            }
    } else {
        #pragma unroll
        for (int mi = 0; mi < 2; mi++) {
            const int row0 = aRow + mi * 16 + g;      // local row ids (same tile)
            const int row1 = row0 + 8;
            #pragma unroll
            for (int nt = 0; nt < 8; nt++) {
                const int gc = bRow + nt * 8 + t4 * 2;
                float e0 = (row0 == gc    ) ? 0.f : ex2f(acc[mi][nt][0]);
                float e1 = (row0 == gc + 1) ? 0.f : ex2f(acc[mi][nt][1]);
                float e2 = (row1 == gc    ) ? 0.f : ex2f(acc[mi][nt][2]);
                float e3 = (row1 == gc + 1) ? 0.f : ex2f(acc[mi][nt][3]);
                rsum[mi][0] += e0 + e1;
                rsum[mi][1] += e2 + e3;
            }
        }
    }
    __syncthreads();                               // tiles no longer needed
    float* red    = (float*)smem;                  // [128][2 wx]
    float* colRed = (float*)(smem + 1024);         // [128][4 wy]

    #pragma unroll
    for (int mi = 0; mi < 2; mi++)
        #pragma unroll
        for (int hrow = 0; hrow < 2; hrow++) {
            float s = rsum[mi][hrow];
            s += __shfl_xor_sync(0xffffffffu, s, 1);
            s += __shfl_xor_sync(0xffffffffu, s, 2);
            if (t4 == 0) red[(aRow + mi * 16 + hrow * 8 + g) * 2 + wx] = s;
        }

    if (offDiag) {
        #pragma unroll
        for (int nt = 0; nt < 8; nt++)
            #pragma unroll
            for (int sc = 0; sc < 2; sc++) {
                float s = cs[nt][sc];
                s += __shfl_xor_sync(0xffffffffu, s, 4);
                s += __shfl_xor_sync(0xffffffffu, s, 8);
                s += __shfl_xor_sync(0xffffffffu, s, 16);
                if (g == 0) colRed[(bRow + nt * 8 + t4 * 2 + sc) * 4 + wy] = s;
            }
    }
    __syncthreads();
    if (tid < 128) {
        g_rowPart[(size_t)ct * N + rowBase + tid] = red[tid * 2] + red[tid * 2 + 1];
        if (offDiag)
            g_rowPart[(size_t)rt * N + colBase + tid] =
                (colRed[tid * 4] + colRed[tid * 4 + 1]) + (colRed[tid * 4 + 2] + colRed[tid * 4 + 3]);
    }
}

// ---------------- 5) row totals (fixed order, deterministic) ----------------
__global__ void rowtot_kernel() {
    int r = blockIdx.x * 256 + threadIdx.x;
    float s = 0.f;
    #pragma unroll
    for (int c = 0; c < NT; c++) s += g_rowPart[(size_t)c * N + r];
    g_rowTot[r] = s;
}

// ---------------- 6) per-class loss: HMMA mini-Gram + loss terms (log2 domain) ----------------
#define CLS_SMEM (128 * LDAB + 128 * SSTR * 4)
__global__ void __launch_bounds__(256, 1) class_loss_kernel() {
    extern __shared__ char cs_[];
    char*  tile = cs_;
    float* S    = (float*)(cs_ + 128 * LDAB);
    __shared__ int   gidx[CAP];
    __shared__ float unsimS[CAP];
    __shared__ float tr[256];
    const uint32_t sb = smem_u32(tile);
    const int c = blockIdx.x, tid = threadIdx.x, wid = tid >> 5, lane = tid & 31;
    const int base = g_ofs[c];
    int n = g_ofs[c + 1] - base;
    if (n > CAP) n = CAP;

    for (int i = tid; i < CAP; i += 256) gidx[i] = (i < n) ? g_order[base + i] : 0;
    __syncthreads();
    for (int i = tid; i < 128 * 16; i += 256) {
        int r = i >> 4, c8 = i & 15;
        uint32_t off = (uint32_t)r * LDAB + (uint32_t)c8 * 16;
        uint4 v = make_uint4(0u, 0u, 0u, 0u);
        if (r < n) v = ((const uint4*)(g_yhi + (size_t)gidx[r] * D))[c8];
        *(uint4*)(tile + off) = v;
    }
    __syncthreads();

    const int wy = wid & 3, wx = wid >> 2;
    const int aRow = wy * 32, bRow = wx * 64;
    const int aR  = aRow + (lane & 15);
    const int aC  = (lane >> 4) * 16;
    const int bR  = bRow + (lane & 7) + ((lane >> 4) << 3);
    const int bC  = ((lane >> 3) & 1) * 16;

    float acc[2][8][4];
    #pragma unroll
    for (int mi = 0; mi < 2; mi++)
        #pragma unroll
        for (int nt = 0; nt < 8; nt++)
            #pragma unroll
            for (int q = 0; q < 4; q++) acc[mi][nt][q] = 0.f;

    #pragma unroll
    for (int kk = 0; kk < 8; kk++) {
        const uint32_t kOff = (uint32_t)kk * 32;
        uint32_t ah[2][4], bh[4][4];
        #pragma unroll
        for (int mi = 0; mi < 2; mi++)
            LDSM4(ah[mi], sb + (uint32_t)(aR + mi * 16) * LDAB + kOff + aC);
        #pragma unroll
        for (int ni = 0; ni < 4; ni++)
            LDSM4(bh[ni], sb + (uint32_t)(bR + ni * 16) * LDAB + kOff + bC);
        #pragma unroll
        for (int mi = 0; mi < 2; mi++)
            #pragma unroll
            for (int ni = 0; ni < 4; ni++)
                #pragma unroll
                for (int h = 0; h < 2; h++)
                    MMA16816(acc[mi][ni * 2 + h], ah[mi], bh[ni][h * 2], bh[ni][h * 2 + 1]);
    }

    const int g = lane >> 2, t4 = lane & 3;
    #pragma unroll
    for (int mi = 0; mi < 2; mi++) {
        const int r0 = aRow + mi * 16 + g;
        #pragma unroll
        for (int nt = 0; nt < 8; nt++) {
            const int col = bRow + nt * 8 + t4 * 2;
            *(float2*)&S[r0 * SSTR + col]       = make_float2(acc[mi][nt][0], acc[mi][nt][1]);
            *(float2*)&S[(r0 + 8) * SSTR + col] = make_float2(acc[mi][nt][2], acc[mi][nt][3]);
        }
    }
    __syncthreads();

    // possum_i -> unsim_i  (S in log2 domain)
    for (int i = wid; i < n; i += 8) {
        float ps = 0.f;
        for (int j = lane; j < n; j += 32)
            if (j != i) ps += ex2f(S[i * SSTR + j]);
        #pragma unroll
        for (int o = 16; o > 0; o >>= 1) ps += __shfl_xor_sync(0xffffffffu, ps, o);
        if (lane == 0) unsimS[i] = g_rowTot[gidx[i]] - ps;
    }
    __syncthreads();

    // loss terms: ln(e+unsim) - s_nat = ln2 * (log2(e+unsim) - S)
    float la = 0.f;
    const int nn = n * n;
    for (int p = tid; p < nn; p += 256) {
        int i = p / n, j = p - i * n;
        if (i == j) continue;
        float s = S[i * SSTR + j];
        la += lg2f(ex2f(s) + unsimS[i]) - s;
    }
    tr[tid] = la * LN2F;
    __syncthreads();
    #pragma unroll
    for (int o = 128; o > 0; o >>= 1) {
        if (tid < o) tr[tid] += tr[tid + o];
        __syncthreads();
    }
    if (tid == 0) { g_classLoss[c] = tr[0]; g_classN[c] = (float)n * (float)(n - 1); }
}

// ---------------- 7) finalize ----------------
__global__ void finalize_kernel(float* __restrict__ out) {
    __shared__ float sl[NCLS], sn[NCLS];
    int t = threadIdx.x;
    sl[t] = g_classLoss[t];
    sn[t] = g_classN[t];
    __syncthreads();
    if (t == 0) {
        float L = 0.f, P = 0.f;
        for (int k = 0; k < NCLS; k++) { L += sl[k]; P += sn[k]; }
        out[0] = L / P;
    }
}

// ---------------- launch ----------------
extern "C" void kernel_launch(void* const* d_in, const int* in_sizes, int n_in,
                              void* d_out, int out_size) {
    const float* x     = (const float*)d_in[0];
    const int*   label = (const int*)d_in[1];
    float*       out   = (float*)d_out;

    cudaFuncSetAttribute(gram_hmma, cudaFuncAttributeMaxDynamicSharedMemorySize, SM_TOTAL);
    cudaFuncSetAttribute(class_loss_kernel, cudaFuncAttributeMaxDynamicSharedMemorySize, CLS_SMEM);

    prep_kernel<<<N / 8, 256>>>(x);
    build_ofs_kernel<<<1, 256>>>(label);
    scatter_kernel<<<NCHUNK, 256>>>(label);
    gram_hmma<<<NTRI, 256, SM_TOTAL>>>();
    rowtot_kernel<<<N / 256, 256>>>();
    class_loss_kernel<<<NCLS, 256, CLS_SMEM>>>();
    finalize_kernel<<<1, NCLS>>>(out);
}